// round 9
// baseline (speedup 1.0000x reference)
#include <cuda_runtime.h>
#include <cuda_bf16.h>

#define Bb   8
#define T    16
#define C    64
#define Hh   56
#define Ww   56
#define HW   3136          // 56*56
#define HW2  1568          // HW/2  (float2 columns per (n,t) slice)
#define DIN  64            // 8*8 pooled
#define DOUT 32            // 2*d_t
#define NBC  512           // b*c
#define NT   (NBC * T)     // 8192 (n,t) slices
#define NCOL2 (NBC * HW2)  // 802816 float2 columns (= 3136 * 256)

// scratch
__device__ float g_flat[NT * DIN];       // pooled features [n*T+t][64], 2MB
__device__ float g_att[NBC * T * T];     // softmaxed attention, 512KB

// ---------------------------------------------------------------------------
// Kernel 1: pooling, warp-autonomous. One block per (n,t) slice; each warp
// owns one bin-row (7 image rows x 56 cols). Proven ~5.5 TB/s (read ceiling).
// ---------------------------------------------------------------------------
__global__ __launch_bounds__(256)
void pool_kernel(const float* __restrict__ x)
{
    const int nt   = blockIdx.x;        // n*T + t
    const int n    = nt >> 4;
    const int t    = nt & 15;
    const int b    = n >> 6;
    const int c    = n & 63;
    const int wid  = threadIdx.x >> 5;  // d1 = bin row, 0..7
    const int lane = threadIdx.x & 31;

    __shared__ float scol[8][56 + 8];   // per-warp column sums (padded)

    const float* slice = x + ((size_t)(b * T + t) * C + c) * HW;
    const float2* rows = (const float2*)(slice + (7 * wid) * Ww);  // 28 f2/row

    if (lane < 28) {
        float2 s = make_float2(0.f, 0.f);
        #pragma unroll
        for (int dh = 0; dh < 7; ++dh) {
            const float2 v = rows[dh * (Ww / 2) + lane];
            s.x += v.x;
            s.y += v.y;
        }
        scol[wid][2 * lane]     = s.x;
        scol[wid][2 * lane + 1] = s.y;
    }
    __syncwarp();

    if (lane < 8) {
        const float* cs = &scol[wid][7 * lane];
        float a0 = cs[0] + cs[1];
        float a1 = cs[2] + cs[3];
        float a2 = cs[4] + cs[5];
        a0 += cs[6];
        g_flat[nt * DIN + wid * 8 + lane] = (a0 + a1 + a2) * (1.f / 49.f);
    }
}

// ---------------------------------------------------------------------------
// Kernel 2: q/k projection + att + register/shuffle softmax. One block per n.
// ---------------------------------------------------------------------------
__global__ __launch_bounds__(256)
void att_kernel(const float* __restrict__ Wq, const float* __restrict__ bq,
                const float* __restrict__ Wk, const float* __restrict__ bk)
{
    const int n   = blockIdx.x;
    const int tid = threadIdx.x;

    __shared__ float flat[T][DIN];           // 4 KB
    __shared__ float sWq[DIN * DOUT];        // 8 KB
    __shared__ float sWk[DIN * DOUT];        // 8 KB
    __shared__ float sq[T][DOUT + 1];
    __shared__ float sk[T][DOUT + 1];

    for (int i = tid; i < DIN * DOUT; i += 256) {
        sWq[i] = Wq[i];
        sWk[i] = Wk[i];
    }
    for (int i = tid; i < T * DIN; i += 256)
        ((float*)flat)[i] = g_flat[n * T * DIN + i];
    __syncthreads();

    for (int i = tid; i < T * DOUT; i += 256) {
        const int tt = i >> 5, j = i & 31;
        float aq = bq[j];
        float ak = bk[j];
        #pragma unroll
        for (int d = 0; d < DIN; ++d) {
            const float f = flat[tt][d];
            aq = fmaf(f, sWq[d * DOUT + j], aq);
            ak = fmaf(f, sWk[d * DOUT + j], ak);
        }
        sq[tt][j] = aq;
        sk[tt][j] = ak;
    }
    __syncthreads();

    const int i = tid >> 4, j = tid & 15;
    float s = 0.f;
    #pragma unroll
    for (int d = 0; d < DOUT; ++d)
        s = fmaf(sq[i][d], sk[j][d], s);
    s *= 0.25f;                          // 1/sqrt(16)

    float m = s;
    #pragma unroll
    for (int k = 8; k >= 1; k >>= 1)
        m = fmaxf(m, __shfl_xor_sync(0xffffffffu, m, k));
    float e = __expf(s - m);
    float ssum = e;
    #pragma unroll
    for (int k = 8; k >= 1; k >>= 1)
        ssum += __shfl_xor_sync(0xffffffffu, ssum, k);

    g_att[n * (T * T) + tid] = e * (1.f / ssum);
}

// ---------------------------------------------------------------------------
// Kernel 3: out[b,t,c,:] = sum_s att[n,t,s] * x[b,s,c,:]
// float2 per thread (v[16] = 32 regs -> ~2x occupancy vs float4 version).
// Reversed n order for L2 reuse of x; __stcs streaming stores.
// ---------------------------------------------------------------------------
__global__ __launch_bounds__(256)
void av_kernel(const float* __restrict__ x, float* __restrict__ out)
{
    const int tid  = threadIdx.x;
    const int gid0 = blockIdx.x << 8;               // first float2-column
    const int n0   = gid0 / HW2;                    // block spans n0 or n0+1

    // stage att rows for the (at most) 2 reversed-n's this block touches
    __shared__ float satt[2][T * T];
    #pragma unroll
    for (int i = tid; i < 2 * T * T; i += 256) {
        const int m   = i >> 8;
        const int idx = i & 255;
        const int nn  = n0 + m;
        satt[m][idx] = (nn < NBC) ? g_att[(NBC - 1 - nn) * (T * T) + idx] : 0.f;
    }
    __syncthreads();

    const int gid = gid0 + tid;
    const int n   = gid / HW2;
    const int p2  = gid - n * HW2;
    const int m   = n - n0;
    const int rn  = NBC - 1 - n;                    // reversed n
    const int b   = rn >> 6;
    const int c   = rn & 63;

    const int stride_s = C * HW2;                   // float2 stride per t/s
    const int base     = (b * T * C + c) * HW2 + p2;
    const float2* xb = (const float2*)x + base;
    float2* ob = (float2*)out + base;

    float2 v[T];
    #pragma unroll
    for (int s = 0; s < T; ++s)
        v[s] = xb[s * stride_s];

    const float* arow = satt[m];
    #pragma unroll
    for (int t = 0; t < T; ++t) {
        float2 a = make_float2(0.f, 0.f);
        #pragma unroll
        for (int s = 0; s < T; ++s) {
            const float w = arow[t * T + s];
            a.x = fmaf(w, v[s].x, a.x);
            a.y = fmaf(w, v[s].y, a.y);
        }
        __stcs(&ob[t * stride_s], a);               // streaming store
    }
}

// ---------------------------------------------------------------------------
extern "C" void kernel_launch(void* const* d_in, const int* in_sizes, int n_in,
                              void* d_out, int out_size)
{
    const float* x  = (const float*)d_in[0];
    const float* Wq = (const float*)d_in[1];
    const float* bq = (const float*)d_in[2];
    const float* Wk = (const float*)d_in[3];
    const float* bk = (const float*)d_in[4];
    float* out = (float*)d_out;

    pool_kernel<<<NT, 256>>>(x);
    att_kernel<<<NBC, 256>>>(Wq, bq, Wk, bk);
    av_kernel<<<NCOL2 / 256, 256>>>(x, out);
}